// round 1
// baseline (speedup 1.0000x reference)
#include <cuda_runtime.h>

#define NNODES 8192
#define EDGES  262144
#define NHEAD  4
#define NEG_FILL -9.0e15f

// ---------------- scratch (no allocations allowed) ----------------
__device__ float g_Wh1[NNODES * 256];
__device__ float g_x  [NNODES * 256];
__device__ float g_Wh2[NNODES * 128];
__device__ float g_s1src[NHEAD * NNODES];
__device__ float g_s1dst[NHEAD * NNODES];
__device__ float g_s2src[NNODES];
__device__ float g_s2dst[NNODES];
__device__ float g_colsum1[256];
__device__ float g_colsum2[128];
__device__ float g_fill[8];              // [0..3] layer1 heads, [4] layer2
__device__ unsigned g_bitmap[NNODES * NNODES / 32];   // 8 MB dedup bitmap
__device__ int g_deg[NNODES];
__device__ int g_rowptr[NNODES + 1];
__device__ int g_fillptr[NNODES];
__device__ int g_col[EDGES];
__device__ unsigned char g_keep[EDGES];

__device__ __forceinline__ float lrelu(float x) { return x > 0.f ? x : 0.2f * x; }
__device__ __forceinline__ float elu(float x)   { return x > 0.f ? x : expm1f(x); }

// ---------------- zero scratch each launch (deterministic) ----------------
__global__ void k_zero() {
    int idx = blockIdx.x * blockDim.x + threadIdx.x;
    if (idx < NNODES * NNODES / 32) g_bitmap[idx] = 0u;
    if (idx < NNODES)  g_deg[idx] = 0;
    if (idx < 256)     g_colsum1[idx] = 0.f;
    if (idx < 128)     g_colsum2[idx] = 0.f;
}

// ---------------- SGEMM: C[M,Nn] = A[M,K] @ B[Nn,K]^T ----------------
// BM=128, BN=64, BK=16, 256 threads, 8x4 register tile.
__global__ void k_gemm(const float* __restrict__ A, const float* __restrict__ B,
                       float* __restrict__ C, int M, int Nn, int K) {
    __shared__ float As[16][132];
    __shared__ float Bs[16][68];
    const int bm = blockIdx.x * 128;
    const int bn = blockIdx.y * 64;
    const int tid = threadIdx.x;
    const int tx = tid & 15;       // n: 4 each -> 64
    const int ty = tid >> 4;       // m: 8 each -> 128

    float acc[8][4];
#pragma unroll
    for (int i = 0; i < 8; i++)
#pragma unroll
        for (int j = 0; j < 4; j++) acc[i][j] = 0.f;

    for (int k0 = 0; k0 < K; k0 += 16) {
        // load A tile 128x16 (512 float4, 2/thread)
#pragma unroll
        for (int q = tid; q < 512; q += 256) {
            int row = q >> 2, seg = q & 3;
            float4 v = *(const float4*)&A[(size_t)(bm + row) * K + k0 + seg * 4];
            As[seg * 4 + 0][row] = v.x; As[seg * 4 + 1][row] = v.y;
            As[seg * 4 + 2][row] = v.z; As[seg * 4 + 3][row] = v.w;
        }
        // load B tile 64x16 (256 float4, 1/thread)
        {
            int q = tid;
            int row = q >> 2, seg = q & 3;
            float4 v = *(const float4*)&B[(size_t)(bn + row) * K + k0 + seg * 4];
            Bs[seg * 4 + 0][row] = v.x; Bs[seg * 4 + 1][row] = v.y;
            Bs[seg * 4 + 2][row] = v.z; Bs[seg * 4 + 3][row] = v.w;
        }
        __syncthreads();
#pragma unroll
        for (int kk = 0; kk < 16; kk++) {
            float4 b4 = *(float4*)&Bs[kk][tx * 4];
            float4 a0 = *(float4*)&As[kk][ty * 8];
            float4 a1 = *(float4*)&As[kk][ty * 8 + 4];
            float a[8] = {a0.x, a0.y, a0.z, a0.w, a1.x, a1.y, a1.z, a1.w};
            float b[4] = {b4.x, b4.y, b4.z, b4.w};
#pragma unroll
            for (int i = 0; i < 8; i++)
#pragma unroll
                for (int j = 0; j < 4; j++) acc[i][j] = fmaf(a[i], b[j], acc[i][j]);
        }
        __syncthreads();
    }
#pragma unroll
    for (int i = 0; i < 8; i++) {
        float4 o = make_float4(acc[i][0], acc[i][1], acc[i][2], acc[i][3]);
        *(float4*)&C[(size_t)(bm + ty * 8 + i) * Nn + bn + tx * 4] = o;
    }
}

// ---------------- column sums of a [NNODES, cols] matrix ----------------
__global__ void k_colsum(const float* __restrict__ src, float* __restrict__ dst, int cols) {
    int c = threadIdx.x;                 // blockDim.x == cols
    int r0 = blockIdx.x * 128;
    float s = 0.f;
    for (int r = r0; r < r0 + 128; r++) s += src[(size_t)r * cols + c];
    atomicAdd(&dst[c], s);
}

// ---------------- per-node attention scalars, layer 1 ----------------
__global__ void k_scalars1(const float* __restrict__ a1) {
    int w = (blockIdx.x * blockDim.x + threadIdx.x) >> 5;
    int lane = threadIdx.x & 31;
    if (w >= NNODES) return;
    const float* wh = &g_Wh1[(size_t)w * 256];
#pragma unroll
    for (int k = 0; k < 4; k++) {
        float x0 = wh[k * 64 + lane], x1 = wh[k * 64 + 32 + lane];
        float vs = x0 * a1[k * 128 + lane]      + x1 * a1[k * 128 + 32 + lane];
        float vd = x0 * a1[k * 128 + 64 + lane] + x1 * a1[k * 128 + 96 + lane];
#pragma unroll
        for (int off = 16; off; off >>= 1) {
            vs += __shfl_xor_sync(0xffffffffu, vs, off);
            vd += __shfl_xor_sync(0xffffffffu, vd, off);
        }
        if (lane == 0) { g_s1src[k * NNODES + w] = vs; g_s1dst[k * NNODES + w] = vd; }
    }
}

// ---------------- per-node attention scalars, layer 2 ----------------
__global__ void k_scalars2(const float* __restrict__ a2) {
    int w = (blockIdx.x * blockDim.x + threadIdx.x) >> 5;
    int lane = threadIdx.x & 31;
    if (w >= NNODES) return;
    const float* wh = &g_Wh2[(size_t)w * 128];
    float vs = 0.f, vd = 0.f;
#pragma unroll
    for (int r = 0; r < 4; r++) {
        float x = wh[lane + 32 * r];
        vs += x * a2[lane + 32 * r];
        vd += x * a2[128 + lane + 32 * r];
    }
#pragma unroll
    for (int off = 16; off; off >>= 1) {
        vs += __shfl_xor_sync(0xffffffffu, vs, off);
        vd += __shfl_xor_sync(0xffffffffu, vd, off);
    }
    if (lane == 0) { g_s2src[w] = vs; g_s2dst[w] = vd; }
}

// ---------------- fill constants ----------------
__global__ void k_fill_consts(const float* __restrict__ a1, const float* __restrict__ a2) {
    int lane = threadIdx.x;  // 32 threads
#pragma unroll
    for (int k = 0; k < 4; k++) {
        float s = 0.f;
        for (int d = lane; d < 128; d += 32) s += a1[k * 128 + d];
#pragma unroll
        for (int off = 16; off; off >>= 1) s += __shfl_xor_sync(0xffffffffu, s, off);
        if (lane == 0) g_fill[k] = lrelu(NEG_FILL * s);
    }
    float s = 0.f;
    for (int d = lane; d < 256; d += 32) s += a2[d];
#pragma unroll
    for (int off = 16; off; off >>= 1) s += __shfl_xor_sync(0xffffffffu, s, off);
    if (lane == 0) g_fill[4] = lrelu(NEG_FILL * s);
}

// ---------------- CSR build with bitmap dedup ----------------
__global__ void k_mark(const int* __restrict__ src, const int* __restrict__ dst) {
    int e = blockIdx.x * blockDim.x + threadIdx.x;
    if (e >= EDGES) return;
    int s = src[e], d = dst[e];
    unsigned idx = (unsigned)s * NNODES + (unsigned)d;
    unsigned mask = 1u << (idx & 31u);
    unsigned old = atomicOr(&g_bitmap[idx >> 5], mask);
    unsigned char keep = (old & mask) ? 0 : 1;
    g_keep[e] = keep;
    if (keep) atomicAdd(&g_deg[s], 1);
}

__global__ void k_scan() {     // 1 block, 1024 threads: exclusive scan of deg[8192]
    __shared__ int sh[1024];
    int t = threadIdx.x;
    int loc[8]; int s = 0;
#pragma unroll
    for (int j = 0; j < 8; j++) { loc[j] = s; s += g_deg[t * 8 + j]; }
    sh[t] = s;
    __syncthreads();
    for (int off = 1; off < 1024; off <<= 1) {
        int v = (t >= off) ? sh[t - off] : 0;
        __syncthreads();
        sh[t] += v;
        __syncthreads();
    }
    int base = (t == 0) ? 0 : sh[t - 1];
#pragma unroll
    for (int j = 0; j < 8; j++) {
        int p = base + loc[j];
        g_rowptr[t * 8 + j] = p;
        g_fillptr[t * 8 + j] = p;
    }
    if (t == 1023) g_rowptr[NNODES] = sh[1023];
}

__global__ void k_fillcsr(const int* __restrict__ src, const int* __restrict__ dst) {
    int e = blockIdx.x * blockDim.x + threadIdx.x;
    if (e >= EDGES) return;
    if (g_keep[e]) {
        int s = src[e];
        int p = atomicAdd(&g_fillptr[s], 1);
        g_col[p] = dst[e];
    }
}

// ---------------- layer-1 aggregation: block per node, warp per head ----------------
__global__ void k_agg1() {
    int i = blockIdx.x;
    int k = threadIdx.x >> 5, lane = threadIdx.x & 31;
    int beg = g_rowptr[i], end = g_rowptr[i + 1];
    float ssrc = g_s1src[k * NNODES + i];
    float fill = g_fill[k];
    float m = fill;
    for (int t = beg + lane; t < end; t += 32) {
        int j = g_col[t];
        m = fmaxf(m, lrelu(ssrc + g_s1dst[k * NNODES + j]));
    }
#pragma unroll
    for (int off = 16; off; off >>= 1) m = fmaxf(m, __shfl_xor_sync(0xffffffffu, m, off));

    float acc0 = 0.f, acc1 = 0.f, an0 = 0.f, an1 = 0.f, ws = 0.f;
    for (int t = beg; t < end; t++) {
        int j = g_col[t];
        float e = lrelu(ssrc + g_s1dst[k * NNODES + j]);
        float wgt = __expf(e - m);
        ws += wgt;
        const float* wh = &g_Wh1[(size_t)j * 256 + k * 64];
        float v0 = wh[lane], v1 = wh[lane + 32];
        acc0 = fmaf(wgt, v0, acc0); acc1 = fmaf(wgt, v1, acc1);
        an0 += v0; an1 += v1;
    }
    float wf = __expf(fill - m);
    int deg = end - beg;
    float denom = ws + (float)(NNODES - deg) * wf;
    float c0 = g_colsum1[k * 64 + lane], c1 = g_colsum1[k * 64 + 32 + lane];
    float o0 = (acc0 + wf * (c0 - an0)) / denom;
    float o1 = (acc1 + wf * (c1 - an1)) / denom;
    g_x[(size_t)i * 256 + k * 64 + lane]      = elu(o0);
    g_x[(size_t)i * 256 + k * 64 + 32 + lane] = elu(o1);
}

// ---------------- layer-2 aggregation: warp per node, 128 dims ----------------
__global__ void k_agg2(float* __restrict__ out) {
    int i = (blockIdx.x * blockDim.x + threadIdx.x) >> 5;
    int lane = threadIdx.x & 31;
    if (i >= NNODES) return;
    int beg = g_rowptr[i], end = g_rowptr[i + 1];
    float ssrc = g_s2src[i];
    float fill = g_fill[4];
    float m = fill;
    for (int t = beg + lane; t < end; t += 32) {
        int j = g_col[t];
        m = fmaxf(m, lrelu(ssrc + g_s2dst[j]));
    }
#pragma unroll
    for (int off = 16; off; off >>= 1) m = fmaxf(m, __shfl_xor_sync(0xffffffffu, m, off));

    float acc[4] = {0.f, 0.f, 0.f, 0.f}, an[4] = {0.f, 0.f, 0.f, 0.f}, ws = 0.f;
    for (int t = beg; t < end; t++) {
        int j = g_col[t];
        float e = lrelu(ssrc + g_s2dst[j]);
        float wgt = __expf(e - m);
        ws += wgt;
        const float* wh = &g_Wh2[(size_t)j * 128];
#pragma unroll
        for (int r = 0; r < 4; r++) {
            float v = wh[lane + 32 * r];
            acc[r] = fmaf(wgt, v, acc[r]);
            an[r] += v;
        }
    }
    float wf = __expf(fill - m);
    int deg = end - beg;
    float denom = ws + (float)(NNODES - deg) * wf;
#pragma unroll
    for (int r = 0; r < 4; r++) {
        float c = g_colsum2[lane + 32 * r];
        float o = (acc[r] + wf * (c - an[r])) / denom;
        o = elu(o);   // head elu
        o = elu(o);   // outer elu
        out[(size_t)i * 128 + lane + 32 * r] = o;
    }
}

// ---------------- launch ----------------
extern "C" void kernel_launch(void* const* d_in, const int* in_sizes, int n_in,
                              void* d_out, int out_size) {
    const float* h   = (const float*)d_in[0];   // [8192,256]
    const float* W1  = (const float*)d_in[1];   // [4,64,256] -> [256,256]
    const float* a1  = (const float*)d_in[2];   // [4,128]
    const float* W2  = (const float*)d_in[3];   // [128,256]
    const float* a2  = (const float*)d_in[4];   // [256]
    const int*  esrc = (const int*)d_in[5];     // [E]
    const int*  edst = (const int*)d_in[6];     // [E]
    float* out = (float*)d_out;

    float *pWh1, *pX, *pWh2;
    cudaGetSymbolAddress((void**)&pWh1, g_Wh1);
    cudaGetSymbolAddress((void**)&pX,   g_x);
    cudaGetSymbolAddress((void**)&pWh2, g_Wh2);
    float *pCs1, *pCs2;
    cudaGetSymbolAddress((void**)&pCs1, g_colsum1);
    cudaGetSymbolAddress((void**)&pCs2, g_colsum2);

    k_zero<<<2048, 1024>>>();

    // CSR build (independent of GEMMs)
    k_mark<<<EDGES / 256, 256>>>(esrc, edst);
    k_scan<<<1, 1024>>>();
    k_fillcsr<<<EDGES / 256, 256>>>(esrc, edst);

    // layer 1
    k_gemm<<<dim3(8192 / 128, 256 / 64), 256>>>(h, W1, pWh1, 8192, 256, 256);
    k_colsum<<<64, 256>>>(pWh1, pCs1, 256);
    k_scalars1<<<1024, 256>>>(a1);
    k_fill_consts<<<1, 32>>>(a1, a2);
    k_agg1<<<8192, 128>>>();

    // layer 2
    k_gemm<<<dim3(8192 / 128, 128 / 64), 256>>>(pX, W2, pWh2, 8192, 128, 256);
    k_colsum<<<64, 128>>>(pWh2, pCs2, 128);
    k_scalars2<<<1024, 256>>>(a2);
    k_agg2<<<1024, 256>>>(out);
}

// round 4
// speedup vs baseline: 1.2158x; 1.2158x over previous
#include <cuda_runtime.h>
#include <cuda_fp16.h>
#include <cstdint>

#define NNODES 8192
#define EDGES  262144
#define NHEAD  4
#define NEG_FILL -9.0e15f

// ---------------- scratch (no allocations allowed) ----------------
__device__ float g_Wh1[NNODES * 256];
__device__ float g_x  [NNODES * 256];
__device__ float g_Wh2[NNODES * 128];
__device__ float g_s1src[NHEAD * NNODES];
__device__ float g_s1dst[NHEAD * NNODES];
__device__ float g_s2src[NNODES];
__device__ float g_s2dst[NNODES];
__device__ float g_colsum1[256];
__device__ float g_colsum2[128];
__device__ float g_fill[8];              // [0..3] layer1 heads, [4] layer2
__device__ unsigned g_bitmap[NNODES * NNODES / 32];   // 8 MB dedup bitmap
__device__ int g_deg[NNODES];
__device__ int g_rowptr[NNODES + 1];
__device__ int g_fillptr[NNODES];
__device__ int g_col[EDGES];
__device__ unsigned char g_keep[EDGES];

__device__ __forceinline__ float lrelu(float x) { return x > 0.f ? x : 0.2f * x; }
__device__ __forceinline__ float elu(float x)   { return x > 0.f ? x : expm1f(x); }

__device__ __forceinline__ uint32_t smem_u32(const void* p) {
    uint32_t a;
    asm("{ .reg .u64 t; cvta.to.shared.u64 t, %1; cvt.u32.u64 %0, t; }" : "=r"(a) : "l"(p));
    return a;
}
__device__ __forceinline__ uint32_t pack_h2(__half a, __half b) {
    __half2 h = __halves2half2(a, b);
    return *reinterpret_cast<uint32_t*>(&h);
}
__device__ __forceinline__ void ldsm4(uint32_t* r, uint32_t addr) {
    asm volatile("ldmatrix.sync.aligned.m8n8.x4.shared.b16 {%0,%1,%2,%3}, [%4];"
                 : "=r"(r[0]), "=r"(r[1]), "=r"(r[2]), "=r"(r[3]) : "r"(addr));
}
__device__ __forceinline__ void mma16816(float* d, const uint32_t* a, uint32_t b0, uint32_t b1) {
    asm volatile("mma.sync.aligned.m16n8k16.row.col.f32.f16.f16.f32 "
                 "{%0,%1,%2,%3}, {%4,%5,%6,%7}, {%8,%9}, {%0,%1,%2,%3};"
                 : "+f"(d[0]), "+f"(d[1]), "+f"(d[2]), "+f"(d[3])
                 : "r"(a[0]), "r"(a[1]), "r"(a[2]), "r"(a[3]), "r"(b0), "r"(b1));
}
// swizzled byte address of 16B chunk `chunk` in row `row` (pitch 128B, SW128-style)
__device__ __forceinline__ uint32_t sw_addr(uint32_t base, int row, int chunk) {
    return base + row * 128 + (((chunk ^ (row & 7)) << 4));
}

// ---------------- zero scratch each launch (deterministic) ----------------
__global__ void k_zero() {
    int idx = blockIdx.x * blockDim.x + threadIdx.x;
    if (idx < NNODES * NNODES / 32) g_bitmap[idx] = 0u;
    if (idx < NNODES)  g_deg[idx] = 0;
    if (idx < 256)     g_colsum1[idx] = 0.f;
    if (idx < 128)     g_colsum2[idx] = 0.f;
}

// ---------------- HMMA GEMM: C[M,Nn] = A[M,256] @ B[Nn,256]^T ----------------
// 128x128 CTA tile, K-chunks of 64 halfs, fp16 hi/lo split (3 MMAs) for ~fp32.
__global__ void __launch_bounds__(256) k_gemm_mma(
    const float* __restrict__ A, const float* __restrict__ B,
    float* __restrict__ C, int Nn)
{
    extern __shared__ char smem[];
    const int K = 256;
    uint32_t sb = smem_u32(smem);
    const uint32_t AHI = 0, ALO = 16384, BHI = 32768, BLO = 49152;
    const int tid = threadIdx.x, lane = tid & 31, wid = tid >> 5;
    const int wm = wid & 3, wn = wid >> 2;          // 4 x 2 warp grid
    const int bm = blockIdx.x * 128, bn = blockIdx.y * 128;

    float acc[2][8][4];
#pragma unroll
    for (int i = 0; i < 2; i++)
#pragma unroll
        for (int j = 0; j < 8; j++)
#pragma unroll
            for (int q = 0; q < 4; q++) acc[i][j][q] = 0.f;

    const int g = lane >> 3, lr = lane & 7;

    for (int kc = 0; kc < 4; kc++) {
        const int kbase = kc * 64;
        // load+convert A and B chunks into swizzled hi/lo smem (8 float4 each)
#pragma unroll
        for (int q = tid; q < 2048; q += 256) {
            int row = q >> 4, seg = q & 15;
            uint32_t off = (uint32_t)row * 128 + ((((seg >> 1) ^ (row & 7)) << 4)) + ((seg & 1) << 3);
            float4 va = *(const float4*)&A[(size_t)(bm + row) * K + kbase + seg * 4];
            __half hx = __float2half_rn(va.x), hy = __float2half_rn(va.y);
            __half hz = __float2half_rn(va.z), hw = __float2half_rn(va.w);
            *(uint2*)(smem + AHI + off) = make_uint2(pack_h2(hx, hy), pack_h2(hz, hw));
            *(uint2*)(smem + ALO + off) = make_uint2(
                pack_h2(__float2half_rn(va.x - __half2float(hx)), __float2half_rn(va.y - __half2float(hy))),
                pack_h2(__float2half_rn(va.z - __half2float(hz)), __float2half_rn(va.w - __half2float(hw))));
            float4 vb = *(const float4*)&B[(size_t)(bn + row) * K + kbase + seg * 4];
            hx = __float2half_rn(vb.x); hy = __float2half_rn(vb.y);
            hz = __float2half_rn(vb.z); hw = __float2half_rn(vb.w);
            *(uint2*)(smem + BHI + off) = make_uint2(pack_h2(hx, hy), pack_h2(hz, hw));
            *(uint2*)(smem + BLO + off) = make_uint2(
                pack_h2(__float2half_rn(vb.x - __half2float(hx)), __float2half_rn(vb.y - __half2float(hy))),
                pack_h2(__float2half_rn(vb.z - __half2float(hz)), __float2half_rn(vb.w - __half2float(hw))));
        }
        __syncthreads();

#pragma unroll
        for (int ks = 0; ks < 4; ks++) {
            const int chunk = ks * 2 + (g >> 1);
            uint32_t ahi[2][4], alo[2][4], bhi[4][4], blo[4][4];
#pragma unroll
            for (int am = 0; am < 2; am++) {
                int row = wm * 32 + am * 16 + (g & 1) * 8 + lr;
                ldsm4(ahi[am], sw_addr(sb + AHI, row, chunk));
                ldsm4(alo[am], sw_addr(sb + ALO, row, chunk));
            }
#pragma unroll
            for (int bp = 0; bp < 4; bp++) {
                int row = wn * 64 + bp * 16 + (g & 1) * 8 + lr;
                ldsm4(bhi[bp], sw_addr(sb + BHI, row, chunk));
                ldsm4(blo[bp], sw_addr(sb + BLO, row, chunk));
            }
#pragma unroll
            for (int am = 0; am < 2; am++)
#pragma unroll
                for (int bp = 0; bp < 4; bp++) {
                    float* c0 = acc[am][bp * 2];
                    float* c1 = acc[am][bp * 2 + 1];
                    mma16816(c0, ahi[am], bhi[bp][0], bhi[bp][2]);
                    mma16816(c1, ahi[am], bhi[bp][1], bhi[bp][3]);
                    mma16816(c0, ahi[am], blo[bp][0], blo[bp][2]);
                    mma16816(c1, ahi[am], blo[bp][1], blo[bp][3]);
                    mma16816(c0, alo[am], bhi[bp][0], bhi[bp][2]);
                    mma16816(c1, alo[am], bhi[bp][1], bhi[bp][3]);
                }
        }
        __syncthreads();
    }

    // epilogue: store C
#pragma unroll
    for (int am = 0; am < 2; am++) {
        int r0 = bm + wm * 32 + am * 16 + (lane >> 2);
        int c0 = bn + wn * 64 + (lane & 3) * 2;
#pragma unroll
        for (int j = 0; j < 8; j++) {
            *(float2*)&C[(size_t)r0 * Nn + c0 + j * 8]       = make_float2(acc[am][j][0], acc[am][j][1]);
            *(float2*)&C[(size_t)(r0 + 8) * Nn + c0 + j * 8] = make_float2(acc[am][j][2], acc[am][j][3]);
        }
    }
}

// ---------------- column sums of a [NNODES, cols] matrix ----------------
__global__ void k_colsum(const float* __restrict__ src, float* __restrict__ dst, int cols) {
    int c = threadIdx.x;                 // blockDim.x == cols
    int r0 = blockIdx.x * 128;
    float s = 0.f;
    for (int r = r0; r < r0 + 128; r++) s += src[(size_t)r * cols + c];
    atomicAdd(&dst[c], s);
}

// ---------------- per-node attention scalars, layer 1 ----------------
__global__ void k_scalars1(const float* __restrict__ a1) {
    int w = (blockIdx.x * blockDim.x + threadIdx.x) >> 5;
    int lane = threadIdx.x & 31;
    if (w >= NNODES) return;
    const float* wh = &g_Wh1[(size_t)w * 256];
#pragma unroll
    for (int k = 0; k < 4; k++) {
        float x0 = wh[k * 64 + lane], x1 = wh[k * 64 + 32 + lane];
        float vs = x0 * a1[k * 128 + lane]      + x1 * a1[k * 128 + 32 + lane];
        float vd = x0 * a1[k * 128 + 64 + lane] + x1 * a1[k * 128 + 96 + lane];
#pragma unroll
        for (int off = 16; off; off >>= 1) {
            vs += __shfl_xor_sync(0xffffffffu, vs, off);
            vd += __shfl_xor_sync(0xffffffffu, vd, off);
        }
        if (lane == 0) { g_s1src[k * NNODES + w] = vs; g_s1dst[k * NNODES + w] = vd; }
    }
}

// ---------------- per-node attention scalars, layer 2 ----------------
__global__ void k_scalars2(const float* __restrict__ a2) {
    int w = (blockIdx.x * blockDim.x + threadIdx.x) >> 5;
    int lane = threadIdx.x & 31;
    if (w >= NNODES) return;
    const float* wh = &g_Wh2[(size_t)w * 128];
    float vs = 0.f, vd = 0.f;
#pragma unroll
    for (int r = 0; r < 4; r++) {
        float x = wh[lane + 32 * r];
        vs += x * a2[lane + 32 * r];
        vd += x * a2[128 + lane + 32 * r];
    }
#pragma unroll
    for (int off = 16; off; off >>= 1) {
        vs += __shfl_xor_sync(0xffffffffu, vs, off);
        vd += __shfl_xor_sync(0xffffffffu, vd, off);
    }
    if (lane == 0) { g_s2src[w] = vs; g_s2dst[w] = vd; }
}

// ---------------- CSR build with bitmap dedup ----------------
__global__ void k_mark(const int* __restrict__ src, const int* __restrict__ dst) {
    int e = blockIdx.x * blockDim.x + threadIdx.x;
    if (e >= EDGES) return;
    int s = src[e], d = dst[e];
    unsigned idx = (unsigned)s * NNODES + (unsigned)d;
    unsigned mask = 1u << (idx & 31u);
    unsigned old = atomicOr(&g_bitmap[idx >> 5], mask);
    unsigned char keep = (old & mask) ? 0 : 1;
    g_keep[e] = keep;
    if (keep) atomicAdd(&g_deg[s], 1);
}

// 1 block, 1024 threads: exclusive scan of deg[8192] + fill constants
__global__ void k_scan(const float* __restrict__ a1, const float* __restrict__ a2) {
    __shared__ int sh[1024];
    int t = threadIdx.x;
    if (t < 32) {
        int lane = t;
#pragma unroll
        for (int k = 0; k < 4; k++) {
            float s = 0.f;
            for (int d = lane; d < 128; d += 32) s += a1[k * 128 + d];
#pragma unroll
            for (int off = 16; off; off >>= 1) s += __shfl_xor_sync(0xffffffffu, s, off);
            if (lane == 0) g_fill[k] = lrelu(NEG_FILL * s);
        }
        float s = 0.f;
        for (int d = lane; d < 256; d += 32) s += a2[d];
#pragma unroll
        for (int off = 16; off; off >>= 1) s += __shfl_xor_sync(0xffffffffu, s, off);
        if (lane == 0) g_fill[4] = lrelu(NEG_FILL * s);
    }
    int loc[8]; int s = 0;
#pragma unroll
    for (int j = 0; j < 8; j++) { loc[j] = s; s += g_deg[t * 8 + j]; }
    sh[t] = s;
    __syncthreads();
    for (int off = 1; off < 1024; off <<= 1) {
        int v = (t >= off) ? sh[t - off] : 0;
        __syncthreads();
        sh[t] += v;
        __syncthreads();
    }
    int base = (t == 0) ? 0 : sh[t - 1];
#pragma unroll
    for (int j = 0; j < 8; j++) {
        int p = base + loc[j];
        g_rowptr[t * 8 + j] = p;
        g_fillptr[t * 8 + j] = p;
    }
    if (t == 1023) g_rowptr[NNODES] = sh[1023];
}

__global__ void k_fillcsr(const int* __restrict__ src, const int* __restrict__ dst) {
    int e = blockIdx.x * blockDim.x + threadIdx.x;
    if (e >= EDGES) return;
    if (g_keep[e]) {
        int s = src[e];
        int p = atomicAdd(&g_fillptr[s], 1);
        g_col[p] = dst[e];
    }
}

// ---------------- layer-1 aggregation: block per node, warp per head ----------------
__global__ void k_agg1() {
    int i = blockIdx.x;
    int k = threadIdx.x >> 5, lane = threadIdx.x & 31;
    int beg = g_rowptr[i], end = g_rowptr[i + 1];
    float ssrc = g_s1src[k * NNODES + i];
    float fill = g_fill[k];
    float m = fill;
    for (int t = beg + lane; t < end; t += 32) {
        int j = g_col[t];
        m = fmaxf(m, lrelu(ssrc + g_s1dst[k * NNODES + j]));
    }
#pragma unroll
    for (int off = 16; off; off >>= 1) m = fmaxf(m, __shfl_xor_sync(0xffffffffu, m, off));

    float acc0 = 0.f, acc1 = 0.f, an0 = 0.f, an1 = 0.f, ws = 0.f;
    for (int t = beg; t < end; t++) {
        int j = g_col[t];
        float e = lrelu(ssrc + g_s1dst[k * NNODES + j]);
        float wgt = __expf(e - m);
        ws += wgt;
        const float* wh = &g_Wh1[(size_t)j * 256 + k * 64];
        float v0 = wh[lane], v1 = wh[lane + 32];
        acc0 = fmaf(wgt, v0, acc0); acc1 = fmaf(wgt, v1, acc1);
        an0 += v0; an1 += v1;
    }
    float wf = __expf(fill - m);
    int deg = end - beg;
    float denom = ws + (float)(NNODES - deg) * wf;
    float c0 = g_colsum1[k * 64 + lane], c1 = g_colsum1[k * 64 + 32 + lane];
    float o0 = (acc0 + wf * (c0 - an0)) / denom;
    float o1 = (acc1 + wf * (c1 - an1)) / denom;
    g_x[(size_t)i * 256 + k * 64 + lane]      = elu(o0);
    g_x[(size_t)i * 256 + k * 64 + 32 + lane] = elu(o1);
}

// ---------------- layer-2 aggregation: warp per node, 128 dims ----------------
__global__ void k_agg2(float* __restrict__ out) {
    int i = (blockIdx.x * blockDim.x + threadIdx.x) >> 5;
    int lane = threadIdx.x & 31;
    if (i >= NNODES) return;
    int beg = g_rowptr[i], end = g_rowptr[i + 1];
    float ssrc = g_s2src[i];
    float fill = g_fill[4];
    float m = fill;
    for (int t = beg + lane; t < end; t += 32) {
        int j = g_col[t];
        m = fmaxf(m, lrelu(ssrc + g_s2dst[j]));
    }
#pragma unroll
    for (int off = 16; off; off >>= 1) m = fmaxf(m, __shfl_xor_sync(0xffffffffu, m, off));

    float acc[4] = {0.f, 0.f, 0.f, 0.f}, an[4] = {0.f, 0.f, 0.f, 0.f}, ws = 0.f;
    for (int t = beg; t < end; t++) {
        int j = g_col[t];
        float e = lrelu(ssrc + g_s2dst[j]);
        float wgt = __expf(e - m);
        ws += wgt;
        const float* wh = &g_Wh2[(size_t)j * 128];
#pragma unroll
        for (int r = 0; r < 4; r++) {
            float v = wh[lane + 32 * r];
            acc[r] = fmaf(wgt, v, acc[r]);
            an[r] += v;
        }
    }
    float wf = __expf(fill - m);
    int deg = end - beg;
    float denom = ws + (float)(NNODES - deg) * wf;
#pragma unroll
    for (int r = 0; r < 4; r++) {
        float c = g_colsum2[lane + 32 * r];
        float o = (acc[r] + wf * (c - an[r])) / denom;
        o = elu(o);   // head elu
        o = elu(o);   // outer elu
        out[(size_t)i * 128 + lane + 32 * r] = o;
    }
}

// ---------------- launch ----------------
extern "C" void kernel_launch(void* const* d_in, const int* in_sizes, int n_in,
                              void* d_out, int out_size) {
    const float* h   = (const float*)d_in[0];   // [8192,256]
    const float* W1  = (const float*)d_in[1];   // [4,64,256] -> [256,256]
    const float* a1  = (const float*)d_in[2];   // [4,128]
    const float* W2  = (const float*)d_in[3];   // [128,256]
    const float* a2  = (const float*)d_in[4];   // [256]
    const int*  esrc = (const int*)d_in[5];     // [E]
    const int*  edst = (const int*)d_in[6];     // [E]
    float* out = (float*)d_out;

    float *pWh1, *pX, *pWh2, *pCs1, *pCs2;
    cudaGetSymbolAddress((void**)&pWh1, g_Wh1);
    cudaGetSymbolAddress((void**)&pX,   g_x);
    cudaGetSymbolAddress((void**)&pWh2, g_Wh2);
    cudaGetSymbolAddress((void**)&pCs1, g_colsum1);
    cudaGetSymbolAddress((void**)&pCs2, g_colsum2);

    const int SMEM_SZ = 65536;
    cudaFuncSetAttribute(k_gemm_mma, cudaFuncAttributeMaxDynamicSharedMemorySize, SMEM_SZ);

    k_zero<<<2048, 1024>>>();

    // CSR build
    k_mark<<<EDGES / 256, 256>>>(esrc, edst);
    k_scan<<<1, 1024>>>(a1, a2);
    k_fillcsr<<<EDGES / 256, 256>>>(esrc, edst);

    // layer 1
    k_gemm_mma<<<dim3(64, 2), 256, SMEM_SZ>>>(h, W1, pWh1, 256);
    k_colsum<<<64, 256>>>(pWh1, pCs1, 256);
    k_scalars1<<<1024, 256>>>(a1);
    k_agg1<<<8192, 128>>>();

    // layer 2
    k_gemm_mma<<<dim3(64, 1), 256, SMEM_SZ>>>(pX, W2, pWh2, 128);
    k_colsum<<<64, 128>>>(pWh2, pCs2, 128);
    k_scalars2<<<1024, 256>>>(a2);
    k_agg2<<<1024, 256>>>(out);
}

// round 5
// speedup vs baseline: 1.2337x; 1.0148x over previous
#include <cuda_runtime.h>
#include <cuda_fp16.h>
#include <cstdint>

#define NNODES 8192
#define EDGES  262144
#define NHEAD  4
#define NEG_FILL -9.0e15f

// ---------------- scratch (no allocations allowed) ----------------
__device__ float  g_Wh1 [NNODES * 256];
__device__ __half g_Wh1h[NNODES * 256];
__device__ float  g_x   [NNODES * 256];
__device__ float  g_Wh2 [NNODES * 128];
__device__ __half g_Wh2h[NNODES * 128];
__device__ float g_s1src[NHEAD * NNODES];
__device__ float g_s1dst[NHEAD * NNODES];
__device__ float g_s2src[NNODES];
__device__ float g_s2dst[NNODES];
__device__ float g_colsum1[256];
__device__ float g_colsum2[128];
__device__ float g_fill[8];              // [0..3] layer1 heads, [4] layer2
__device__ unsigned g_bitmap[NNODES * NNODES / 32];   // 8 MB dedup bitmap
__device__ int g_deg[NNODES];
__device__ int g_rowptr[NNODES + 1];
__device__ int g_fillptr[NNODES];
__device__ int g_col[EDGES];
__device__ unsigned char g_keep[EDGES];

__device__ __forceinline__ float lrelu(float x) { return x > 0.f ? x : 0.2f * x; }
__device__ __forceinline__ float elu(float x)   { return x > 0.f ? x : expm1f(x); }

__device__ __forceinline__ uint32_t smem_u32(const void* p) {
    uint32_t a;
    asm("{ .reg .u64 t; cvta.to.shared.u64 t, %1; cvt.u32.u64 %0, t; }" : "=r"(a) : "l"(p));
    return a;
}
__device__ __forceinline__ uint32_t pack_h2(__half a, __half b) {
    __half2 h = __halves2half2(a, b);
    return *reinterpret_cast<uint32_t*>(&h);
}
__device__ __forceinline__ void ldsm4(uint32_t* r, uint32_t addr) {
    asm volatile("ldmatrix.sync.aligned.m8n8.x4.shared.b16 {%0,%1,%2,%3}, [%4];"
                 : "=r"(r[0]), "=r"(r[1]), "=r"(r[2]), "=r"(r[3]) : "r"(addr));
}
__device__ __forceinline__ void mma16816(float* d, const uint32_t* a, uint32_t b0, uint32_t b1) {
    asm volatile("mma.sync.aligned.m16n8k16.row.col.f32.f16.f16.f32 "
                 "{%0,%1,%2,%3}, {%4,%5,%6,%7}, {%8,%9}, {%0,%1,%2,%3};"
                 : "+f"(d[0]), "+f"(d[1]), "+f"(d[2]), "+f"(d[3])
                 : "r"(a[0]), "r"(a[1]), "r"(a[2]), "r"(a[3]), "r"(b0), "r"(b1));
}
__device__ __forceinline__ uint32_t sw_addr(uint32_t base, int row, int chunk) {
    return base + row * 128 + (((chunk ^ (row & 7)) << 4));
}

// ---------------- zero scratch each launch (deterministic) ----------------
__global__ void k_zero() {
    int idx = blockIdx.x * blockDim.x + threadIdx.x;
    if (idx < NNODES * NNODES / 32) g_bitmap[idx] = 0u;
    if (idx < NNODES)  g_deg[idx] = 0;
    if (idx < 256)     g_colsum1[idx] = 0.f;
    if (idx < 128)     g_colsum2[idx] = 0.f;
}

// ---------------- HMMA GEMM: C[M,Nn] = A[M,256] @ B[Nn,256]^T ----------------
// 128x128 CTA tile, K-chunks of 64 halfs, fp16 hi/lo split (3 MMAs) for ~fp32.
// Also emits fp16 copy of C for the gather-heavy aggregation kernels.
__global__ void __launch_bounds__(256) k_gemm_mma(
    const float* __restrict__ A, const float* __restrict__ B,
    float* __restrict__ C, __half* __restrict__ Ch, int Nn)
{
    extern __shared__ char smem[];
    const int K = 256;
    uint32_t sb = smem_u32(smem);
    const uint32_t AHI = 0, ALO = 16384, BHI = 32768, BLO = 49152;
    const int tid = threadIdx.x, lane = tid & 31, wid = tid >> 5;
    const int wm = wid & 3, wn = wid >> 2;          // 4 x 2 warp grid
    const int bm = blockIdx.x * 128, bn = blockIdx.y * 128;

    float acc[2][8][4];
#pragma unroll
    for (int i = 0; i < 2; i++)
#pragma unroll
        for (int j = 0; j < 8; j++)
#pragma unroll
            for (int q = 0; q < 4; q++) acc[i][j][q] = 0.f;

    const int g = lane >> 3, lr = lane & 7;

    for (int kc = 0; kc < 4; kc++) {
        const int kbase = kc * 64;
#pragma unroll
        for (int q = tid; q < 2048; q += 256) {
            int row = q >> 4, seg = q & 15;
            uint32_t off = (uint32_t)row * 128 + ((((seg >> 1) ^ (row & 7)) << 4)) + ((seg & 1) << 3);
            float4 va = *(const float4*)&A[(size_t)(bm + row) * K + kbase + seg * 4];
            __half hx = __float2half_rn(va.x), hy = __float2half_rn(va.y);
            __half hz = __float2half_rn(va.z), hw = __float2half_rn(va.w);
            *(uint2*)(smem + AHI + off) = make_uint2(pack_h2(hx, hy), pack_h2(hz, hw));
            *(uint2*)(smem + ALO + off) = make_uint2(
                pack_h2(__float2half_rn(va.x - __half2float(hx)), __float2half_rn(va.y - __half2float(hy))),
                pack_h2(__float2half_rn(va.z - __half2float(hz)), __float2half_rn(va.w - __half2float(hw))));
            float4 vb = *(const float4*)&B[(size_t)(bn + row) * K + kbase + seg * 4];
            hx = __float2half_rn(vb.x); hy = __float2half_rn(vb.y);
            hz = __float2half_rn(vb.z); hw = __float2half_rn(vb.w);
            *(uint2*)(smem + BHI + off) = make_uint2(pack_h2(hx, hy), pack_h2(hz, hw));
            *(uint2*)(smem + BLO + off) = make_uint2(
                pack_h2(__float2half_rn(vb.x - __half2float(hx)), __float2half_rn(vb.y - __half2float(hy))),
                pack_h2(__float2half_rn(vb.z - __half2float(hz)), __float2half_rn(vb.w - __half2float(hw))));
        }
        __syncthreads();

#pragma unroll
        for (int ks = 0; ks < 4; ks++) {
            const int chunk = ks * 2 + (g >> 1);
            uint32_t ahi[2][4], alo[2][4], bhi[4][4], blo[4][4];
#pragma unroll
            for (int am = 0; am < 2; am++) {
                int row = wm * 32 + am * 16 + (g & 1) * 8 + lr;
                ldsm4(ahi[am], sw_addr(sb + AHI, row, chunk));
                ldsm4(alo[am], sw_addr(sb + ALO, row, chunk));
            }
#pragma unroll
            for (int bp = 0; bp < 4; bp++) {
                int row = wn * 64 + bp * 16 + (g & 1) * 8 + lr;
                ldsm4(bhi[bp], sw_addr(sb + BHI, row, chunk));
                ldsm4(blo[bp], sw_addr(sb + BLO, row, chunk));
            }
#pragma unroll
            for (int am = 0; am < 2; am++)
#pragma unroll
                for (int bp = 0; bp < 4; bp++) {
                    float* c0 = acc[am][bp * 2];
                    float* c1 = acc[am][bp * 2 + 1];
                    mma16816(c0, ahi[am], bhi[bp][0], bhi[bp][2]);
                    mma16816(c1, ahi[am], bhi[bp][1], bhi[bp][3]);
                    mma16816(c0, ahi[am], blo[bp][0], blo[bp][2]);
                    mma16816(c1, ahi[am], blo[bp][1], blo[bp][3]);
                    mma16816(c0, alo[am], bhi[bp][0], bhi[bp][2]);
                    mma16816(c1, alo[am], bhi[bp][1], bhi[bp][3]);
                }
        }
        __syncthreads();
    }

    // epilogue: store C (fp32) + Ch (fp16)
#pragma unroll
    for (int am = 0; am < 2; am++) {
        int r0 = bm + wm * 32 + am * 16 + (lane >> 2);
        int c0 = bn + wn * 64 + (lane & 3) * 2;
#pragma unroll
        for (int j = 0; j < 8; j++) {
            *(float2*)&C[(size_t)r0 * Nn + c0 + j * 8]       = make_float2(acc[am][j][0], acc[am][j][1]);
            *(float2*)&C[(size_t)(r0 + 8) * Nn + c0 + j * 8] = make_float2(acc[am][j][2], acc[am][j][3]);
            __half2 h0 = __floats2half2_rn(acc[am][j][0], acc[am][j][1]);
            __half2 h1 = __floats2half2_rn(acc[am][j][2], acc[am][j][3]);
            *(__half2*)&Ch[(size_t)r0 * Nn + c0 + j * 8]       = h0;
            *(__half2*)&Ch[(size_t)(r0 + 8) * Nn + c0 + j * 8] = h1;
        }
    }
}

// ---------------- fused colsum + per-row attention scalars ----------------
// COLS: row width (256 or 128), HW: head width (64 or 128).
template <int COLS, int HW>
__global__ void __launch_bounds__(256) k_stats(
    const float* __restrict__ Wh, const float* __restrict__ avec,
    float* __restrict__ colsum, float* __restrict__ ssrc, float* __restrict__ sdst)
{
    constexpr int LSPAN = COLS / 32;     // cols per lane (8 or 4)
    constexpr int SEG   = HW / LSPAN;    // lanes per head segment (8 or 32)
    __shared__ float sA[2 * COLS];
    __shared__ float scol[COLS];
    const int tid = threadIdx.x, lane = tid & 31, wid = tid >> 5;

    for (int q = tid; q < COLS; q += 256) {
        int hh = q / HW, d = q % HW;
        sA[q]        = avec[hh * 2 * HW + d];
        sA[COLS + q] = avec[hh * 2 * HW + HW + d];
        scol[q] = 0.f;
    }
    __syncthreads();

    float as[LSPAN], ad[LSPAN], cs[LSPAN];
#pragma unroll
    for (int r = 0; r < LSPAN; r++) {
        as[r] = sA[lane * LSPAN + r];
        ad[r] = sA[COLS + lane * LSPAN + r];
        cs[r] = 0.f;
    }
    const int head = lane / SEG;

    for (int row = blockIdx.x * 8 + wid; row < NNODES; row += gridDim.x * 8) {
        const float* wr = &Wh[(size_t)row * COLS + lane * LSPAN];
        float v[LSPAN];
#pragma unroll
        for (int r = 0; r < LSPAN; r += 4)
            *(float4*)&v[r] = *(const float4*)&wr[r];
        float ps = 0.f, pd = 0.f;
#pragma unroll
        for (int r = 0; r < LSPAN; r++) {
            cs[r] += v[r];
            ps = fmaf(v[r], as[r], ps);
            pd = fmaf(v[r], ad[r], pd);
        }
#pragma unroll
        for (int off = SEG / 2; off; off >>= 1) {
            ps += __shfl_xor_sync(0xffffffffu, ps, off);
            pd += __shfl_xor_sync(0xffffffffu, pd, off);
        }
        if ((lane & (SEG - 1)) == 0) {
            ssrc[(size_t)head * NNODES + row] = ps;
            sdst[(size_t)head * NNODES + row] = pd;
        }
    }
    __syncthreads();
#pragma unroll
    for (int r = 0; r < LSPAN; r++) atomicAdd(&scol[lane * LSPAN + r], cs[r]);
    __syncthreads();
    for (int q = tid; q < COLS; q += 256) atomicAdd(&colsum[q], scol[q]);
}

// ---------------- CSR build with bitmap dedup ----------------
__global__ void k_mark(const int* __restrict__ src, const int* __restrict__ dst) {
    int e = blockIdx.x * blockDim.x + threadIdx.x;
    if (e >= EDGES) return;
    int s = src[e], d = dst[e];
    unsigned idx = (unsigned)s * NNODES + (unsigned)d;
    unsigned mask = 1u << (idx & 31u);
    unsigned old = atomicOr(&g_bitmap[idx >> 5], mask);
    unsigned char keep = (old & mask) ? 0 : 1;
    g_keep[e] = keep;
    if (keep) atomicAdd(&g_deg[s], 1);
}

// 1 block, 1024 threads: exclusive scan of deg[8192] + fill constants
__global__ void k_scan(const float* __restrict__ a1, const float* __restrict__ a2) {
    __shared__ int sh[1024];
    int t = threadIdx.x;
    if (t < 32) {
        int lane = t;
#pragma unroll
        for (int k = 0; k < 4; k++) {
            float s = 0.f;
            for (int d = lane; d < 128; d += 32) s += a1[k * 128 + d];
#pragma unroll
            for (int off = 16; off; off >>= 1) s += __shfl_xor_sync(0xffffffffu, s, off);
            if (lane == 0) g_fill[k] = lrelu(NEG_FILL * s);
        }
        float s = 0.f;
        for (int d = lane; d < 256; d += 32) s += a2[d];
#pragma unroll
        for (int off = 16; off; off >>= 1) s += __shfl_xor_sync(0xffffffffu, s, off);
        if (lane == 0) g_fill[4] = lrelu(NEG_FILL * s);
    }
    int loc[8]; int s = 0;
#pragma unroll
    for (int j = 0; j < 8; j++) { loc[j] = s; s += g_deg[t * 8 + j]; }
    sh[t] = s;
    __syncthreads();
    for (int off = 1; off < 1024; off <<= 1) {
        int v = (t >= off) ? sh[t - off] : 0;
        __syncthreads();
        sh[t] += v;
        __syncthreads();
    }
    int base = (t == 0) ? 0 : sh[t - 1];
#pragma unroll
    for (int j = 0; j < 8; j++) {
        int p = base + loc[j];
        g_rowptr[t * 8 + j] = p;
        g_fillptr[t * 8 + j] = p;
    }
    if (t == 1023) g_rowptr[NNODES] = sh[1023];
}

__global__ void k_fillcsr(const int* __restrict__ src, const int* __restrict__ dst) {
    int e = blockIdx.x * blockDim.x + threadIdx.x;
    if (e >= EDGES) return;
    if (g_keep[e]) {
        int s = src[e];
        int p = atomicAdd(&g_fillptr[s], 1);
        g_col[p] = dst[e];
    }
}

// ---------------- layer-1 aggregation: block per node, warp per head (fp16 gather) ----------------
__global__ void k_agg1() {
    int i = blockIdx.x;
    int k = threadIdx.x >> 5, lane = threadIdx.x & 31;
    int beg = g_rowptr[i], end = g_rowptr[i + 1];
    float ssrc = g_s1src[k * NNODES + i];
    float fill = g_fill[k];
    float m = fill;
    for (int t = beg + lane; t < end; t += 32) {
        int j = g_col[t];
        m = fmaxf(m, lrelu(ssrc + g_s1dst[k * NNODES + j]));
    }
#pragma unroll
    for (int off = 16; off; off >>= 1) m = fmaxf(m, __shfl_xor_sync(0xffffffffu, m, off));

    float acc0 = 0.f, acc1 = 0.f, an0 = 0.f, an1 = 0.f, ws = 0.f;
    for (int t = beg; t < end; t++) {
        int j = g_col[t];
        float e = lrelu(ssrc + g_s1dst[k * NNODES + j]);
        float wgt = __expf(e - m);
        ws += wgt;
        __half2 v = *(const __half2*)&g_Wh1h[(size_t)j * 256 + k * 64 + 2 * lane];
        float2 vf = __half22float2(v);
        acc0 = fmaf(wgt, vf.x, acc0); acc1 = fmaf(wgt, vf.y, acc1);
        an0 += vf.x; an1 += vf.y;
    }
    float wf = __expf(fill - m);
    int deg = end - beg;
    float denom = ws + (float)(NNODES - deg) * wf;
    float c0 = g_colsum1[k * 64 + 2 * lane], c1 = g_colsum1[k * 64 + 2 * lane + 1];
    float o0 = (acc0 + wf * (c0 - an0)) / denom;
    float o1 = (acc1 + wf * (c1 - an1)) / denom;
    g_x[(size_t)i * 256 + k * 64 + 2 * lane]     = elu(o0);
    g_x[(size_t)i * 256 + k * 64 + 2 * lane + 1] = elu(o1);
}

// ---------------- layer-2 aggregation: warp per node, 128 dims (fp16 gather) ----------------
__global__ void k_agg2(float* __restrict__ out) {
    int i = (blockIdx.x * blockDim.x + threadIdx.x) >> 5;
    int lane = threadIdx.x & 31;
    if (i >= NNODES) return;
    int beg = g_rowptr[i], end = g_rowptr[i + 1];
    float ssrc = g_s2src[i];
    float fill = g_fill[4];
    float m = fill;
    for (int t = beg + lane; t < end; t += 32) {
        int j = g_col[t];
        m = fmaxf(m, lrelu(ssrc + g_s2dst[j]));
    }
#pragma unroll
    for (int off = 16; off; off >>= 1) m = fmaxf(m, __shfl_xor_sync(0xffffffffu, m, off));

    float acc[4] = {0.f, 0.f, 0.f, 0.f}, an[4] = {0.f, 0.f, 0.f, 0.f}, ws = 0.f;
    for (int t = beg; t < end; t++) {
        int j = g_col[t];
        float e = lrelu(ssrc + g_s2dst[j]);
        float wgt = __expf(e - m);
        ws += wgt;
        uint2 u = *(const uint2*)&g_Wh2h[(size_t)j * 128 + 4 * lane];
        float2 va = __half22float2(*(__half2*)&u.x);
        float2 vb = __half22float2(*(__half2*)&u.y);
        acc[0] = fmaf(wgt, va.x, acc[0]); an[0] += va.x;
        acc[1] = fmaf(wgt, va.y, acc[1]); an[1] += va.y;
        acc[2] = fmaf(wgt, vb.x, acc[2]); an[2] += vb.x;
        acc[3] = fmaf(wgt, vb.y, acc[3]); an[3] += vb.y;
    }
    float wf = __expf(fill - m);
    int deg = end - beg;
    float denom = ws + (float)(NNODES - deg) * wf;
#pragma unroll
    for (int r = 0; r < 4; r++) {
        float c = g_colsum2[4 * lane + r];
        float o = (acc[r] + wf * (c - an[r])) / denom;
        o = elu(o);   // head elu
        o = elu(o);   // outer elu
        out[(size_t)i * 128 + 4 * lane + r] = o;
    }
}

// ---------------- launch ----------------
extern "C" void kernel_launch(void* const* d_in, const int* in_sizes, int n_in,
                              void* d_out, int out_size) {
    const float* h   = (const float*)d_in[0];   // [8192,256]
    const float* W1  = (const float*)d_in[1];   // [4,64,256] -> [256,256]
    const float* a1  = (const float*)d_in[2];   // [4,128]
    const float* W2  = (const float*)d_in[3];   // [128,256]
    const float* a2  = (const float*)d_in[4];   // [256]
    const int*  esrc = (const int*)d_in[5];     // [E]
    const int*  edst = (const int*)d_in[6];     // [E]
    float* out = (float*)d_out;

    float *pWh1, *pX, *pWh2, *pCs1, *pCs2;
    float *pS1s, *pS1d, *pS2s, *pS2d;
    __half *pWh1h, *pWh2h;
    cudaGetSymbolAddress((void**)&pWh1,  g_Wh1);
    cudaGetSymbolAddress((void**)&pWh1h, g_Wh1h);
    cudaGetSymbolAddress((void**)&pX,    g_x);
    cudaGetSymbolAddress((void**)&pWh2,  g_Wh2);
    cudaGetSymbolAddress((void**)&pWh2h, g_Wh2h);
    cudaGetSymbolAddress((void**)&pCs1,  g_colsum1);
    cudaGetSymbolAddress((void**)&pCs2,  g_colsum2);
    cudaGetSymbolAddress((void**)&pS1s,  g_s1src);
    cudaGetSymbolAddress((void**)&pS1d,  g_s1dst);
    cudaGetSymbolAddress((void**)&pS2s,  g_s2src);
    cudaGetSymbolAddress((void**)&pS2d,  g_s2dst);

    const int SMEM_SZ = 65536;
    cudaFuncSetAttribute(k_gemm_mma, cudaFuncAttributeMaxDynamicSharedMemorySize, SMEM_SZ);

    k_zero<<<2048, 1024>>>();

    // CSR build
    k_mark<<<EDGES / 256, 256>>>(esrc, edst);
    k_scan<<<1, 1024>>>(a1, a2);
    k_fillcsr<<<EDGES / 256, 256>>>(esrc, edst);

    // layer 1
    k_gemm_mma<<<dim3(64, 2), 256, SMEM_SZ>>>(h, W1, pWh1, pWh1h, 256);
    k_stats<256, 64><<<128, 256>>>(pWh1, a1, pCs1, pS1s, pS1d);
    k_agg1<<<8192, 128>>>();

    // layer 2
    k_gemm_mma<<<dim3(64, 1), 256, SMEM_SZ>>>(pX, W2, pWh2, pWh2h, 128);
    k_stats<128, 128><<<128, 256>>>(pWh2, a2, pCs2, pS2s, pS2d);
    k_agg2<<<1024, 256>>>(out);
}